// round 15
// baseline (speedup 1.0000x reference)
#include <cuda_runtime.h>
#include <cuda_fp16.h>
#include <math.h>
#include <stdint.h>

#define NB 4096
#define NN 12288          // 3*B
#define MS 10
#define DMSG 384
#define DKIN 484
#define EE 81920
#define NU 50000

#define RPB 64            // mail rows per k2a block
#define NCH 16            // 16 chunks * 32 = K padded to 512
#define NBLK ((NN*MS)/RPB)  // 1920

#define NSCB ((NU + 255) / 256)        // 196 scan blocks

// ---- device scratch (static; no allocation allowed) ----
__device__ float    g_Q[NN * 128];
__device__ uint32_t g_Bh[NCH * 4096];             // fp16x2 B, slot-permuted (256 KB)
__device__ uint32_t g_KVh[(size_t)NN * MS * 128]; // 62.9 MB K|V as half2
__device__ int      g_cnt_i[NU];
__device__ int      g_base[NU];
__device__ int      g_cursor[NU];
__device__ int      g_blksum[256];
__device__ int      g_elist[EE];

// ---------------- helpers ----------------
__device__ __forceinline__ uint32_t s2u(const void* p) {
    uint32_t a;
    asm("{ .reg .u64 t; cvta.to.shared.u64 t, %1; cvt.u32.u64 %0, t; }" : "=r"(a) : "l"(p));
    return a;
}
__device__ __forceinline__ uint32_t packh2(float lo, float hi) {
    __half2 h = __floats2half2_rn(lo, hi);
    return *(uint32_t*)&h;
}
// m16n8k16 fp16 MMA, fp32 accum
__device__ __forceinline__ void mma16(float* d, uint32_t a0, uint32_t a1,
                                      uint32_t a2, uint32_t a3,
                                      uint32_t b0, uint32_t b1) {
    asm volatile(
        "mma.sync.aligned.m16n8k16.row.col.f32.f16.f16.f32 "
        "{%0,%1,%2,%3},{%4,%5,%6,%7},{%8,%9},{%0,%1,%2,%3};"
        : "+f"(d[0]), "+f"(d[1]), "+f"(d[2]), "+f"(d[3])
        : "r"(a0), "r"(a1), "r"(a2), "r"(a3), "r"(b0), "r"(b1));
}

// =====================================================================
// K0b: Wkv -> fp16x2, slot-permuted k-pair layout.
// =====================================================================
__global__ void k0b_bsw(const float* __restrict__ wk, const float* __restrict__ wv) {
    int g = blockIdx.x * 256 + threadIdx.x;   // 65536
    int kc = g >> 12;
    int rem = g & 4095;
    int n = rem >> 4, s = rem & 15;
    int p = (s & 3) * 4 + (s >> 2);
    int k = kc * 32 + 2 * p;
    float v0 = 0.f, v1 = 0.f;
    if (k < DKIN)     v0 = (n < 128) ? wk[k * 128 + n] : wv[k * 128 + (n - 128)];
    if (k + 1 < DKIN) v1 = (n < 128) ? wk[(k + 1) * 128 + n] : wv[(k + 1) * 128 + (n - 128)];
    g_Bh[g] = packh2(v0, v1);
}

// =====================================================================
// K1: Q = mem_table[nodes] @ wq_w + wq_b
// =====================================================================
__global__ void __launch_bounds__(128) k1_q(
    const int* __restrict__ nodes, const float* __restrict__ mem_table,
    const float* __restrict__ wq_w, const float* __restrict__ wq_b)
{
    __shared__ float xs[32 * 128];
    __shared__ int snode[32];
    const int tid = threadIdx.x, blk = blockIdx.x;
    if (tid < 32) snode[tid] = nodes[blk * 32 + tid];
    __syncthreads();
#pragma unroll
    for (int r = 0; r < 32; r++)
        xs[r * 128 + tid] = mem_table[(size_t)snode[r] * 128 + tid];
    __syncthreads();
    float acc[32];
#pragma unroll
    for (int r = 0; r < 32; r++) acc[r] = 0.f;
    for (int k = 0; k < 128; k += 4) {
        float w0 = wq_w[(k + 0) * 128 + tid];
        float w1 = wq_w[(k + 1) * 128 + tid];
        float w2 = wq_w[(k + 2) * 128 + tid];
        float w3 = wq_w[(k + 3) * 128 + tid];
#pragma unroll
        for (int r = 0; r < 32; r++) {
            float4 x = *(const float4*)&xs[r * 128 + k];
            acc[r] += x.x * w0 + x.y * w1 + x.z * w2 + x.w * w3;
        }
    }
    float b = wq_b[tid];
#pragma unroll
    for (int r = 0; r < 32; r++)
        g_Q[(size_t)(blk * 32 + r) * 128 + tid] = acc[r] + b;
}

// =====================================================================
// K2a: fp16 mma.sync GEMM KV[64x256] = A[64x512] @ B[512x256]
// cpB for chunk kc+1 issued BEFORE compute(kc): L2 latency hidden.
// =====================================================================
__global__ void __launch_bounds__(256, 2) k2a_gemm(
    const int* __restrict__ nodes, const float* __restrict__ times,
    const float* __restrict__ mail_table, const float* __restrict__ mail_time,
    const float* __restrict__ te_w, const float* __restrict__ te_b)
{
    __shared__ float steW[100], steB[100], rowDt[64];
    __shared__ int rowOff[64];
    __shared__ uint32_t Ash[2][64 * 16];    // 8 KB
    __shared__ uint32_t Bsh[2][256 * 16];   // 32 KB

    const int tid = threadIdx.x, blk = blockIdx.x;
    const int lane = tid & 31, wid = tid >> 5;
    const int warpM = wid & 1, warpN = wid >> 1;
    const int qr = lane >> 2, lk = lane & 3;

    if (tid < 100) { steW[tid] = te_w[tid]; steB[tid] = te_b[tid]; }
    if (tid < RPB) {
        int g = blk * RPB + tid;
        int ng = g / 10, mi = g - ng * 10;
        int nd = nodes[ng];
        rowOff[tid] = (nd * MS + mi) * DMSG;
        rowDt[tid]  = times[ng] - mail_time[nd * MS + mi];
    }
    __syncthreads();

    float acc[2][8][4];
#pragma unroll
    for (int i = 0; i < 2; i++)
#pragma unroll
        for (int j = 0; j < 8; j++)
#pragma unroll
            for (int c = 0; c < 4; c++) acc[i][j][c] = 0.f;

    uint32_t ah[2][2];
    auto genA = [&](int kc) {
#pragma unroll
        for (int i = 0; i < 2; i++) {
            int f = tid + i * 256;          // [0,512)
            int r = f >> 3, q = f & 7;
            int kbase = kc * 32 + q * 4;
            float4 v;
            if (kc < 12) {
                v = __ldg((const float4*)(mail_table + rowOff[r] + kbase));
            } else {
                int j0 = kbase - 384;
                float dt = rowDt[r];
                v.x = (j0 + 0 < 100) ? cosf(dt * steW[j0 + 0] + steB[j0 + 0]) : 0.f;
                v.y = (j0 + 1 < 100) ? cosf(dt * steW[j0 + 1] + steB[j0 + 1]) : 0.f;
                v.z = (j0 + 2 < 100) ? cosf(dt * steW[j0 + 2] + steB[j0 + 2]) : 0.f;
                v.w = (j0 + 3 < 100) ? cosf(dt * steW[j0 + 3] + steB[j0 + 3]) : 0.f;
            }
            ah[i][0] = packh2(v.x, v.y);
            ah[i][1] = packh2(v.z, v.w);
        }
    };
    auto stsA = [&](int st) {
#pragma unroll
        for (int i = 0; i < 2; i++) {
            int f = tid + i * 256;
            int r = f >> 3, q = f & 7;
            uint32_t* base = &Ash[st][r * 16];
            int p0 = 2 * q, p1 = 2 * q + 1;
            base[(p0 & 3) * 4 + (p0 >> 2)] = ah[i][0];
            base[(p1 & 3) * 4 + (p1 >> 2)] = ah[i][1];
        }
    };
    const uint32_t bshAddr = s2u(&Bsh[0][0]);
    auto cpB = [&](int kc, int st) {
        const uint32_t* src = g_Bh + kc * 4096;
#pragma unroll
        for (int i = 0; i < 4; i++) {
            int u4 = tid + i * 256;
            uint32_t dst = bshAddr + (uint32_t)st * 16384 + (uint32_t)u4 * 16;
            asm volatile("cp.async.ca.shared.global [%0], [%1], 16;"
                         :: "r"(dst), "l"(src + u4 * 4) : "memory");
        }
        asm volatile("cp.async.commit_group;" ::: "memory");
    };
    auto compute = [&](int st) {
        const uint32_t* Ab = &Ash[st][0];
        const uint32_t* Bb = &Bsh[st][0];
        uint4 ua[2][2];
#pragma unroll
        for (int mi = 0; mi < 2; mi++) {
            int row = warpM * 32 + mi * 16 + qr;
            ua[mi][0] = *(const uint4*)&Ab[row * 16 + lk * 4];
            ua[mi][1] = *(const uint4*)&Ab[(row + 8) * 16 + lk * 4];
        }
#pragma unroll
        for (int h = 0; h < 2; h++) {
            uint4 vb[4];
#pragma unroll
            for (int j = 0; j < 4; j++) {
                int n = warpN * 64 + (h * 4 + j) * 8 + qr;
                vb[j] = *(const uint4*)&Bb[n * 16 + lk * 4];
            }
#pragma unroll
            for (int j = 0; j < 4; j++) {
                int ni = h * 4 + j;
                mma16(acc[0][ni], ua[0][0].x, ua[0][1].x, ua[0][0].y, ua[0][1].y,
                      vb[j].x, vb[j].y);
                mma16(acc[1][ni], ua[1][0].x, ua[1][1].x, ua[1][0].y, ua[1][1].y,
                      vb[j].x, vb[j].y);
                mma16(acc[0][ni], ua[0][0].z, ua[0][1].z, ua[0][0].w, ua[0][1].w,
                      vb[j].z, vb[j].w);
                mma16(acc[1][ni], ua[1][0].z, ua[1][1].z, ua[1][0].w, ua[1][1].w,
                      vb[j].z, vb[j].w);
            }
        }
    };

    genA(0);
    stsA(0);
    cpB(0, 0);
    asm volatile("cp.async.wait_group 0;" ::: "memory");
    __syncthreads();

#pragma unroll 1
    for (int kc = 0; kc < NCH; kc++) {
        const int st = kc & 1;
        if (kc < NCH - 1) {
            cpB(kc + 1, st ^ 1);   // issue EARLY: L2 latency hides under compute
            genA(kc + 1);          // LDG gather latency hides under compute
        }
        compute(st);
        if (kc < NCH - 1) {
            stsA(st ^ 1);
            asm volatile("cp.async.wait_group 0;" ::: "memory");
            __syncthreads();
        }
    }

    // write C to g_KVh as half2 (adjacent-column pairs)
#pragma unroll
    for (int mi = 0; mi < 2; mi++) {
#pragma unroll
        for (int ni = 0; ni < 8; ni++) {
            size_t row0 = (size_t)blk * RPB + warpM * 32 + mi * 16 + qr;
            int h2 = warpN * 32 + ni * 4 + lk;      // half2 column index
            g_KVh[row0 * 128 + h2] = packh2(acc[mi][ni][0], acc[mi][ni][1]);
            g_KVh[(row0 + 8) * 128 + h2] = packh2(acc[mi][ni][2], acc[mi][ni][3]);
        }
    }
}

// =====================================================================
// K2b: attention epilogue. 32 nodes/block, warp = 4 nodes.
// mlp_w staged via cp.async, overlapped with the attention phase.
// =====================================================================
#define K2B_NODES 32
#define K2B_SMEM ((16384 + K2B_NODES * 128) * 4)   // 64KB ws + 16KB ysm
__global__ void __launch_bounds__(256) k2b_epi(
    const int* __restrict__ nodes, const float* __restrict__ mem_table,
    const float* __restrict__ wk_b, const float* __restrict__ wv_b,
    const float* __restrict__ ln_g, const float* __restrict__ ln_b,
    const float* __restrict__ mlp_w, const float* __restrict__ mlp_b,
    float* __restrict__ mem_out)
{
    extern __shared__ float smf[];
    float* ws  = smf;                  // 16384 (mlp_w)
    float* ysm = smf + 16384;          // 32*128
    const int tid = threadIdx.x, blk = blockIdx.x;

    // stage mlp_w asynchronously; overlaps the whole attention phase
    {
        uint32_t wsAddr = s2u(ws);
#pragma unroll
        for (int i = 0; i < 16; i++) {
            int e = tid + i * 256;
            asm volatile("cp.async.ca.shared.global [%0], [%1], 16;"
                         :: "r"(wsAddr + (uint32_t)e * 16), "l"(mlp_w + e * 4) : "memory");
        }
        asm volatile("cp.async.commit_group;" ::: "memory");
    }

    const int w = tid >> 5, lane = tid & 31;
    const int c0 = lane * 4;
    float4 kb = *(const float4*)&wk_b[c0];
    float4 vb = *(const float4*)&wv_b[c0];
    float4 g4 = *(const float4*)&ln_g[c0];
    float4 b4 = *(const float4*)&ln_b[c0];

#pragma unroll 1
    for (int it = 0; it < 4; it++) {
        const int nrow = w * 4 + it;
        const int ng = blk * K2B_NODES + nrow;
        float4 q = *(const float4*)&g_Q[(size_t)ng * 128 + c0];
        const uint32_t* kvb = g_KVh + (size_t)ng * MS * 128;

        float a[10];
#pragma unroll
        for (int m = 0; m < 10; m++) {
            uint2 u = *(const uint2*)&kvb[m * 128 + lane * 2];
            float2 f0 = __half22float2(*(__half2*)&u.x);
            float2 f1 = __half22float2(*(__half2*)&u.y);
            float p = (f0.x + kb.x) * q.x + (f0.y + kb.y) * q.y +
                      (f1.x + kb.z) * q.z + (f1.y + kb.w) * q.w;
            p += __shfl_xor_sync(0xffffffffu, p, 8);
            p += __shfl_xor_sync(0xffffffffu, p, 4);
            p += __shfl_xor_sync(0xffffffffu, p, 2);
            p += __shfl_xor_sync(0xffffffffu, p, 1);
            a[m] = p;
        }
        float mx = -1e30f;
#pragma unroll
        for (int m = 0; m < 10; m++) {
            a[m] = (a[m] > 0.f) ? a[m] : 0.2f * a[m];
            mx = fmaxf(mx, a[m]);
        }
        float ssum = 0.f;
#pragma unroll
        for (int m = 0; m < 10; m++) { a[m] = __expf(a[m] - mx); ssum += a[m]; }
        float inv = 1.f / ssum;

        float ox = 0.f, oy = 0.f, oz = 0.f, ow = 0.f;
#pragma unroll
        for (int m = 0; m < 10; m++) {
            uint2 u = *(const uint2*)&kvb[m * 128 + 64 + lane * 2];
            float2 f0 = __half22float2(*(__half2*)&u.x);
            float2 f1 = __half22float2(*(__half2*)&u.y);
            ox += a[m] * (f0.x + vb.x); oy += a[m] * (f0.y + vb.y);
            oz += a[m] * (f1.x + vb.z); ow += a[m] * (f1.y + vb.w);
        }
        ox *= inv; oy *= inv; oz *= inv; ow *= inv;

        int node = nodes[ng];
        float4 md = *(const float4*)&mem_table[(size_t)node * 128 + c0];
        ox += md.x; oy += md.y; oz += md.z; ow += md.w;

        float s1 = ox + oy + oz + ow;
        float s2 = ox * ox + oy * oy + oz * oz + ow * ow;
#pragma unroll
        for (int off = 16; off > 0; off >>= 1) {
            s1 += __shfl_xor_sync(0xffffffffu, s1, off);
            s2 += __shfl_xor_sync(0xffffffffu, s2, off);
        }
        float mu = s1 * (1.f / 128.f);
        float var = s2 * (1.f / 128.f) - mu * mu;
        float rs = rsqrtf(var + 1e-5f);
        float4 y;
        y.x = (ox - mu) * rs * g4.x + b4.x;
        y.y = (oy - mu) * rs * g4.y + b4.y;
        y.z = (oz - mu) * rs * g4.z + b4.z;
        y.w = (ow - mu) * rs * g4.w + b4.w;
        *(float4*)&ysm[nrow * 128 + c0] = y;
    }

    asm volatile("cp.async.wait_group 0;" ::: "memory");
    __syncthreads();

    float4 mb = *(const float4*)&mlp_b[c0];
#pragma unroll 1
    for (int it = 0; it < 4; it++) {
        const int nrow = w * 4 + it;
        float4 accO = mb;
#pragma unroll 8
        for (int k = 0; k < 128; k += 4) {
            float4 yv = *(const float4*)&ysm[nrow * 128 + k];
            float4 w0 = *(const float4*)&ws[(k + 0) * 128 + c0];
            float4 w1 = *(const float4*)&ws[(k + 1) * 128 + c0];
            float4 w2 = *(const float4*)&ws[(k + 2) * 128 + c0];
            float4 w3 = *(const float4*)&ws[(k + 3) * 128 + c0];
            accO.x += yv.x * w0.x + yv.y * w1.x + yv.z * w2.x + yv.w * w3.x;
            accO.y += yv.x * w0.y + yv.y * w1.y + yv.z * w2.y + yv.w * w3.y;
            accO.z += yv.x * w0.z + yv.y * w1.z + yv.z * w2.z + yv.w * w3.z;
            accO.w += yv.x * w0.w + yv.y * w1.w + yv.z * w2.w + yv.w * w3.w;
        }
        accO.x = fmaxf(accO.x, 0.f); accO.y = fmaxf(accO.y, 0.f);
        accO.z = fmaxf(accO.z, 0.f); accO.w = fmaxf(accO.w, 0.f);
        *(float4*)&mem_out[(size_t)(blk * K2B_NODES + nrow) * 128 + c0] = accO;
    }
}

// =====================================================================
// K3: link head
// =====================================================================
__global__ void __launch_bounds__(128) k3_link(
    const float* __restrict__ mem_out,
    const float* __restrict__ src_w, const float* __restrict__ src_b,
    const float* __restrict__ dst_w, const float* __restrict__ dst_b,
    const float* __restrict__ out_w, const float* __restrict__ out_b,
    float* __restrict__ pos, float* __restrict__ neg)
{
    __shared__ float xsS[16 * 128], xsD[16 * 128], xsN[16 * 128];
    __shared__ float redP[16][4], redN[16][4];
    const int tid = threadIdx.x, blk = blockIdx.x;
    const int r0 = blk * 16;
#pragma unroll
    for (int r = 0; r < 16; r++) {
        xsS[r * 128 + tid] = mem_out[(size_t)(r0 + r) * 128 + tid];
        xsD[r * 128 + tid] = mem_out[(size_t)(NB + r0 + r) * 128 + tid];
        xsN[r * 128 + tid] = mem_out[(size_t)(2 * NB + r0 + r) * 128 + tid];
    }
    __syncthreads();
    float aS[16], aD[16], aN[16];
#pragma unroll
    for (int r = 0; r < 16; r++) { aS[r] = 0.f; aD[r] = 0.f; aN[r] = 0.f; }
    for (int k = 0; k < 128; k += 4) {
        float ws0 = src_w[(k + 0) * 128 + tid], ws1 = src_w[(k + 1) * 128 + tid];
        float ws2 = src_w[(k + 2) * 128 + tid], ws3 = src_w[(k + 3) * 128 + tid];
        float wd0 = dst_w[(k + 0) * 128 + tid], wd1 = dst_w[(k + 1) * 128 + tid];
        float wd2 = dst_w[(k + 2) * 128 + tid], wd3 = dst_w[(k + 3) * 128 + tid];
#pragma unroll
        for (int r = 0; r < 16; r++) {
            float4 s = *(const float4*)&xsS[r * 128 + k];
            float4 d = *(const float4*)&xsD[r * 128 + k];
            float4 n = *(const float4*)&xsN[r * 128 + k];
            aS[r] += s.x * ws0 + s.y * ws1 + s.z * ws2 + s.w * ws3;
            aD[r] += d.x * wd0 + d.y * wd1 + d.z * wd2 + d.w * wd3;
            aN[r] += n.x * wd0 + n.y * wd1 + n.z * wd2 + n.w * wd3;
        }
    }
    float ow = out_w[tid];
    float sb = src_b[tid], db = dst_b[tid];
    const int lane = tid & 31, warp = tid >> 5;
#pragma unroll
    for (int r = 0; r < 16; r++) {
        float hs = aS[r] + sb;
        float vP = fmaxf(hs + aD[r] + db, 0.f) * ow;
        float vN = fmaxf(hs + aN[r] + db, 0.f) * ow;
#pragma unroll
        for (int off = 16; off > 0; off >>= 1) {
            vP += __shfl_xor_sync(0xffffffffu, vP, off);
            vN += __shfl_xor_sync(0xffffffffu, vN, off);
        }
        if (lane == 0) { redP[r][warp] = vP; redN[r][warp] = vN; }
    }
    __syncthreads();
    float ob = out_b[0];
    if (tid < 16)
        pos[r0 + tid] = redP[tid][0] + redP[tid][1] + redP[tid][2] + redP[tid][3] + ob;
    else if (tid < 32) {
        int r = tid - 16;
        neg[r0 + r] = redN[r][0] + redN[r][1] + redN[r][2] + redN[r][3] + ob;
    }
}

// =====================================================================
// K4: CSR-style segment mean
// =====================================================================
__global__ void k4_zero() {
    int g = blockIdx.x * 256 + threadIdx.x;
    if (g < NU) g_cnt_i[g] = 0;
}

__global__ void k4_count(const int* __restrict__ src_seg) {
    int e = blockIdx.x * 256 + threadIdx.x;
    if (e < EE) atomicAdd(&g_cnt_i[src_seg[e]], 1);
}

__global__ void __launch_bounds__(256) k4_scan1() {
    __shared__ int smi[256];
    const int tid = threadIdx.x;
    int s = blockIdx.x * 256 + tid;
    int v = (s < NU) ? g_cnt_i[s] : 0;
    smi[tid] = v; __syncthreads();
    int acc = v;
#pragma unroll
    for (int off = 1; off < 256; off <<= 1) {
        int t = (tid >= off) ? smi[tid - off] : 0;
        __syncthreads();
        acc += t; smi[tid] = acc;
        __syncthreads();
    }
    if (s < NU) g_base[s] = acc - v;
    if (tid == 255) g_blksum[blockIdx.x] = acc;
}

__global__ void __launch_bounds__(256) k4_scan2() {
    __shared__ int smi[256];
    const int tid = threadIdx.x;
    int v = (tid < NSCB) ? g_blksum[tid] : 0;
    smi[tid] = v; __syncthreads();
    int acc = v;
#pragma unroll
    for (int off = 1; off < 256; off <<= 1) {
        int t = (tid >= off) ? smi[tid - off] : 0;
        __syncthreads();
        acc += t; smi[tid] = acc;
        __syncthreads();
    }
    if (tid < NSCB) g_blksum[tid] = acc - v;
}

__global__ void k4_scan3() {
    int s = blockIdx.x * 256 + threadIdx.x;
    if (s < NU) {
        int b = g_base[s] + g_blksum[s >> 8];
        g_base[s] = b;
        g_cursor[s] = b;
    }
}

__global__ void k4_scatter(const int* __restrict__ src_seg) {
    int e = blockIdx.x * 256 + threadIdx.x;
    if (e < EE) {
        int slot = atomicAdd(&g_cursor[src_seg[e]], 1);
        g_elist[slot] = e;
    }
}

__global__ void __launch_bounds__(256) k4_gather(
    const int* __restrict__ dstindex, const float* __restrict__ times,
    const float* __restrict__ mem_out, const float* __restrict__ efeat,
    float* __restrict__ o_mail, float* __restrict__ o_ts)
{
    int s = blockIdx.x * 8 + (threadIdx.x >> 5);
    if (s >= NU) return;
    const int lane = threadIdx.x & 31;
    const int c0 = lane * 4;
    int cnt = g_cnt_i[s];
    int base = g_base[s];
    float4 a0 = make_float4(0.f, 0.f, 0.f, 0.f);
    float4 a1 = a0, a2 = a0;
    float tsum = 0.f;
    for (int j = 0; j < cnt; j++) {
        int e = g_elist[base + j];
        int idx = __ldg(&dstindex[e]);
        int other = (idx < NB) ? idx + NB : idx - NB;
        int eb    = (idx < NB) ? idx : idx - NB;
        float4 v0 = *(const float4*)&mem_out[(size_t)idx * 128 + c0];
        float4 v1 = *(const float4*)&mem_out[(size_t)other * 128 + c0];
        float4 v2 = *(const float4*)&efeat[(size_t)eb * 128 + c0];
        a0.x += v0.x; a0.y += v0.y; a0.z += v0.z; a0.w += v0.w;
        a1.x += v1.x; a1.y += v1.y; a1.z += v1.z; a1.w += v1.w;
        a2.x += v2.x; a2.y += v2.y; a2.z += v2.z; a2.w += v2.w;
        tsum += __ldg(&times[idx]);
    }
    float inv = 1.f / fmaxf((float)cnt, 1.f);
    a0.x *= inv; a0.y *= inv; a0.z *= inv; a0.w *= inv;
    a1.x *= inv; a1.y *= inv; a1.z *= inv; a1.w *= inv;
    a2.x *= inv; a2.y *= inv; a2.z *= inv; a2.w *= inv;
    float* dp = o_mail + (size_t)s * 384;
    *(float4*)(dp + c0)       = a0;
    *(float4*)(dp + 128 + c0) = a1;
    *(float4*)(dp + 256 + c0) = a2;
    if (lane == 0) o_ts[s] = tsum * inv;
}

// =====================================================================
extern "C" void kernel_launch(void* const* d_in, const int* in_sizes, int n_in,
                              void* d_out, int out_size)
{
    const int*   nodes      = (const int*)  d_in[0];
    const float* times      = (const float*)d_in[1];
    const float* mem_table  = (const float*)d_in[2];
    const float* mail_table = (const float*)d_in[3];
    const float* mail_time  = (const float*)d_in[4];
    const float* efeat      = (const float*)d_in[5];
    const float* wq_w = (const float*)d_in[6],  *wq_b = (const float*)d_in[7];
    const float* wk_w = (const float*)d_in[8],  *wk_b = (const float*)d_in[9];
    const float* wv_w = (const float*)d_in[10], *wv_b = (const float*)d_in[11];
    const float* mlp_w = (const float*)d_in[12],*mlp_b = (const float*)d_in[13];
    const float* ln_g = (const float*)d_in[14], *ln_b = (const float*)d_in[15];
    const float* te_w = (const float*)d_in[16], *te_b = (const float*)d_in[17];
    const float* src_w = (const float*)d_in[18],*src_b = (const float*)d_in[19];
    const float* dst_w = (const float*)d_in[20],*dst_b = (const float*)d_in[21];
    const float* out_w = (const float*)d_in[22],*out_b = (const float*)d_in[23];
    const int* dstindex = (const int*)d_in[24];
    const int* src_seg  = (const int*)d_in[25];

    float* out    = (float*)d_out;
    float* o_mem  = out;                               // N*128
    float* o_pos  = out + (size_t)NN * 128;            // B
    float* o_neg  = o_pos + NB;                        // B
    float* o_mail = o_neg + NB;                        // NU*384
    float* o_ts   = o_mail + (size_t)NU * 384;         // NU

    static cudaStream_t sSide = nullptr;
    static cudaEvent_t eFork = nullptr, ePrep = nullptr, eMem = nullptr, eSide = nullptr;
    if (!sSide) {
        cudaStreamCreateWithFlags(&sSide, cudaStreamNonBlocking);
        cudaEventCreateWithFlags(&eFork, cudaEventDisableTiming);
        cudaEventCreateWithFlags(&ePrep, cudaEventDisableTiming);
        cudaEventCreateWithFlags(&eMem,  cudaEventDisableTiming);
        cudaEventCreateWithFlags(&eSide, cudaEventDisableTiming);
        cudaFuncSetAttribute(k2b_epi, cudaFuncAttributeMaxDynamicSharedMemorySize, K2B_SMEM);
    }

    // fork: side stream runs k1 + CSR prep concurrently with k0b+k2a
    cudaEventRecord(eFork, 0);
    cudaStreamWaitEvent(sSide, eFork, 0);

    // side stream: Q projection + segment CSR prep
    k1_q<<<NN / 32, 128, 0, sSide>>>(nodes, mem_table, wq_w, wq_b);
    k4_zero<<<NSCB, 256, 0, sSide>>>();
    k4_count<<<EE / 256, 256, 0, sSide>>>(src_seg);
    k4_scan1<<<NSCB, 256, 0, sSide>>>();
    k4_scan2<<<1, 256, 0, sSide>>>();
    k4_scan3<<<NSCB, 256, 0, sSide>>>();
    k4_scatter<<<EE / 256, 256, 0, sSide>>>(src_seg);
    cudaEventRecord(ePrep, sSide);

    // main stream: GEMM
    k0b_bsw<<<256, 256>>>(wk_w, wv_w);
    k2a_gemm<<<NBLK, 256>>>(nodes, times, mail_table, mail_time, te_w, te_b);

    // join: k2b needs g_Q (side) + g_KVh (main)
    cudaStreamWaitEvent(0, ePrep, 0);
    k2b_epi<<<NN / K2B_NODES, 256, K2B_SMEM>>>(nodes, mem_table, wk_b, wv_b,
                                               ln_g, ln_b, mlp_w, mlp_b, o_mem);
    cudaEventRecord(eMem, 0);

    // fork consumers of mem_out: k4_gather on side, k3 on main
    cudaStreamWaitEvent(sSide, eMem, 0);
    k4_gather<<<NU / 8, 256, 0, sSide>>>(dstindex, times, o_mem, efeat, o_mail, o_ts);
    cudaEventRecord(eSide, sSide);

    k3_link<<<NB / 16, 128>>>(o_mem, src_w, src_b, dst_w, dst_b, out_w, out_b,
                              o_pos, o_neg);

    // final join
    cudaStreamWaitEvent(0, eSide, 0);
}

// round 16
// speedup vs baseline: 1.4531x; 1.4531x over previous
#include <cuda_runtime.h>
#include <cuda_fp16.h>
#include <math.h>
#include <stdint.h>

#define NB 4096
#define NN 12288          // 3*B
#define MS 10
#define DMSG 384
#define DKIN 484
#define EE 81920
#define NU 50000

#define RPB 64            // mail rows per k2a block
#define NCH 16            // 16 chunks * 32 = K padded to 512
#define NBLK ((NN*MS)/RPB)  // 1920

#define NSCB ((NU + 255) / 256)        // 196 scan blocks

// ---- device scratch (static; no allocation allowed) ----
__device__ float    g_Q[NN * 128];
__device__ uint32_t g_Bh[NCH * 4096];             // fp16x2 B, slot-permuted (256 KB)
__device__ uint32_t g_KVh[(size_t)NN * MS * 128]; // 62.9 MB K|V as half2
__device__ int      g_cnt_i[NU];
__device__ int      g_base[NU];
__device__ int      g_cursor[NU];
__device__ int      g_blksum[256];
__device__ int      g_elist[EE];

// ---------------- helpers ----------------
__device__ __forceinline__ uint32_t s2u(const void* p) {
    uint32_t a;
    asm("{ .reg .u64 t; cvta.to.shared.u64 t, %1; cvt.u32.u64 %0, t; }" : "=r"(a) : "l"(p));
    return a;
}
__device__ __forceinline__ uint32_t packh2(float lo, float hi) {
    __half2 h = __floats2half2_rn(lo, hi);
    return *(uint32_t*)&h;
}
// m16n8k16 fp16 MMA, fp32 accum
__device__ __forceinline__ void mma16(float* d, uint32_t a0, uint32_t a1,
                                      uint32_t a2, uint32_t a3,
                                      uint32_t b0, uint32_t b1) {
    asm volatile(
        "mma.sync.aligned.m16n8k16.row.col.f32.f16.f16.f32 "
        "{%0,%1,%2,%3},{%4,%5,%6,%7},{%8,%9},{%0,%1,%2,%3};"
        : "+f"(d[0]), "+f"(d[1]), "+f"(d[2]), "+f"(d[3])
        : "r"(a0), "r"(a1), "r"(a2), "r"(a3), "r"(b0), "r"(b1));
}

// =====================================================================
// K0b: Wkv -> fp16x2, slot-permuted k-pair layout.
// =====================================================================
__global__ void k0b_bsw(const float* __restrict__ wk, const float* __restrict__ wv) {
    int g = blockIdx.x * 256 + threadIdx.x;   // 65536
    int kc = g >> 12;
    int rem = g & 4095;
    int n = rem >> 4, s = rem & 15;
    int p = (s & 3) * 4 + (s >> 2);
    int k = kc * 32 + 2 * p;
    float v0 = 0.f, v1 = 0.f;
    if (k < DKIN)     v0 = (n < 128) ? wk[k * 128 + n] : wv[k * 128 + (n - 128)];
    if (k + 1 < DKIN) v1 = (n < 128) ? wk[(k + 1) * 128 + n] : wv[(k + 1) * 128 + (n - 128)];
    g_Bh[g] = packh2(v0, v1);
}

// =====================================================================
// K1: Q = mem_table[nodes] @ wq_w + wq_b
// =====================================================================
__global__ void __launch_bounds__(128) k1_q(
    const int* __restrict__ nodes, const float* __restrict__ mem_table,
    const float* __restrict__ wq_w, const float* __restrict__ wq_b)
{
    __shared__ float xs[32 * 128];
    __shared__ int snode[32];
    const int tid = threadIdx.x, blk = blockIdx.x;
    if (tid < 32) snode[tid] = nodes[blk * 32 + tid];
    __syncthreads();
#pragma unroll
    for (int r = 0; r < 32; r++)
        xs[r * 128 + tid] = mem_table[(size_t)snode[r] * 128 + tid];
    __syncthreads();
    float acc[32];
#pragma unroll
    for (int r = 0; r < 32; r++) acc[r] = 0.f;
    for (int k = 0; k < 128; k += 4) {
        float w0 = wq_w[(k + 0) * 128 + tid];
        float w1 = wq_w[(k + 1) * 128 + tid];
        float w2 = wq_w[(k + 2) * 128 + tid];
        float w3 = wq_w[(k + 3) * 128 + tid];
#pragma unroll
        for (int r = 0; r < 32; r++) {
            float4 x = *(const float4*)&xs[r * 128 + k];
            acc[r] += x.x * w0 + x.y * w1 + x.z * w2 + x.w * w3;
        }
    }
    float b = wq_b[tid];
#pragma unroll
    for (int r = 0; r < 32; r++)
        g_Q[(size_t)(blk * 32 + r) * 128 + tid] = acc[r] + b;
}

// =====================================================================
// K2a: fp16 mma.sync GEMM KV[64x256] = A[64x512] @ B[512x256]
// cpB for chunk kc+1 issued BEFORE compute(kc): L2 latency hidden.
// =====================================================================
__global__ void __launch_bounds__(256, 2) k2a_gemm(
    const int* __restrict__ nodes, const float* __restrict__ times,
    const float* __restrict__ mail_table, const float* __restrict__ mail_time,
    const float* __restrict__ te_w, const float* __restrict__ te_b)
{
    __shared__ float steW[100], steB[100], rowDt[64];
    __shared__ int rowOff[64];
    __shared__ uint32_t Ash[2][64 * 16];    // 8 KB
    __shared__ uint32_t Bsh[2][256 * 16];   // 32 KB

    const int tid = threadIdx.x, blk = blockIdx.x;
    const int lane = tid & 31, wid = tid >> 5;
    const int warpM = wid & 1, warpN = wid >> 1;
    const int qr = lane >> 2, lk = lane & 3;

    if (tid < 100) { steW[tid] = te_w[tid]; steB[tid] = te_b[tid]; }
    if (tid < RPB) {
        int g = blk * RPB + tid;
        int ng = g / 10, mi = g - ng * 10;
        int nd = nodes[ng];
        rowOff[tid] = (nd * MS + mi) * DMSG;
        rowDt[tid]  = times[ng] - mail_time[nd * MS + mi];
    }
    __syncthreads();

    float acc[2][8][4];
#pragma unroll
    for (int i = 0; i < 2; i++)
#pragma unroll
        for (int j = 0; j < 8; j++)
#pragma unroll
            for (int c = 0; c < 4; c++) acc[i][j][c] = 0.f;

    uint32_t ah[2][2];
    auto genA = [&](int kc) {
#pragma unroll
        for (int i = 0; i < 2; i++) {
            int f = tid + i * 256;          // [0,512)
            int r = f >> 3, q = f & 7;
            int kbase = kc * 32 + q * 4;
            float4 v;
            if (kc < 12) {
                v = __ldg((const float4*)(mail_table + rowOff[r] + kbase));
            } else {
                int j0 = kbase - 384;
                float dt = rowDt[r];
                v.x = (j0 + 0 < 100) ? cosf(dt * steW[j0 + 0] + steB[j0 + 0]) : 0.f;
                v.y = (j0 + 1 < 100) ? cosf(dt * steW[j0 + 1] + steB[j0 + 1]) : 0.f;
                v.z = (j0 + 2 < 100) ? cosf(dt * steW[j0 + 2] + steB[j0 + 2]) : 0.f;
                v.w = (j0 + 3 < 100) ? cosf(dt * steW[j0 + 3] + steB[j0 + 3]) : 0.f;
            }
            ah[i][0] = packh2(v.x, v.y);
            ah[i][1] = packh2(v.z, v.w);
        }
    };
    auto stsA = [&](int st) {
#pragma unroll
        for (int i = 0; i < 2; i++) {
            int f = tid + i * 256;
            int r = f >> 3, q = f & 7;
            uint32_t* base = &Ash[st][r * 16];
            int p0 = 2 * q, p1 = 2 * q + 1;
            base[(p0 & 3) * 4 + (p0 >> 2)] = ah[i][0];
            base[(p1 & 3) * 4 + (p1 >> 2)] = ah[i][1];
        }
    };
    const uint32_t bshAddr = s2u(&Bsh[0][0]);
    auto cpB = [&](int kc, int st) {
        const uint32_t* src = g_Bh + kc * 4096;
#pragma unroll
        for (int i = 0; i < 4; i++) {
            int u4 = tid + i * 256;
            uint32_t dst = bshAddr + (uint32_t)st * 16384 + (uint32_t)u4 * 16;
            asm volatile("cp.async.ca.shared.global [%0], [%1], 16;"
                         :: "r"(dst), "l"(src + u4 * 4) : "memory");
        }
        asm volatile("cp.async.commit_group;" ::: "memory");
    };
    auto compute = [&](int st) {
        const uint32_t* Ab = &Ash[st][0];
        const uint32_t* Bb = &Bsh[st][0];
        uint4 ua[2][2];
#pragma unroll
        for (int mi = 0; mi < 2; mi++) {
            int row = warpM * 32 + mi * 16 + qr;
            ua[mi][0] = *(const uint4*)&Ab[row * 16 + lk * 4];
            ua[mi][1] = *(const uint4*)&Ab[(row + 8) * 16 + lk * 4];
        }
#pragma unroll
        for (int h = 0; h < 2; h++) {
            uint4 vb[4];
#pragma unroll
            for (int j = 0; j < 4; j++) {
                int n = warpN * 64 + (h * 4 + j) * 8 + qr;
                vb[j] = *(const uint4*)&Bb[n * 16 + lk * 4];
            }
#pragma unroll
            for (int j = 0; j < 4; j++) {
                int ni = h * 4 + j;
                mma16(acc[0][ni], ua[0][0].x, ua[0][1].x, ua[0][0].y, ua[0][1].y,
                      vb[j].x, vb[j].y);
                mma16(acc[1][ni], ua[1][0].x, ua[1][1].x, ua[1][0].y, ua[1][1].y,
                      vb[j].x, vb[j].y);
                mma16(acc[0][ni], ua[0][0].z, ua[0][1].z, ua[0][0].w, ua[0][1].w,
                      vb[j].z, vb[j].w);
                mma16(acc[1][ni], ua[1][0].z, ua[1][1].z, ua[1][0].w, ua[1][1].w,
                      vb[j].z, vb[j].w);
            }
        }
    };

    genA(0);
    stsA(0);
    cpB(0, 0);
    asm volatile("cp.async.wait_group 0;" ::: "memory");
    __syncthreads();

#pragma unroll 1
    for (int kc = 0; kc < NCH; kc++) {
        const int st = kc & 1;
        if (kc < NCH - 1) {
            cpB(kc + 1, st ^ 1);   // issue EARLY: L2 latency hides under compute
            genA(kc + 1);          // LDG gather latency hides under compute
        }
        compute(st);
        if (kc < NCH - 1) {
            stsA(st ^ 1);
            asm volatile("cp.async.wait_group 0;" ::: "memory");
            __syncthreads();
        }
    }

    // write C to g_KVh as half2 (adjacent-column pairs)
#pragma unroll
    for (int mi = 0; mi < 2; mi++) {
#pragma unroll
        for (int ni = 0; ni < 8; ni++) {
            size_t row0 = (size_t)blk * RPB + warpM * 32 + mi * 16 + qr;
            int h2 = warpN * 32 + ni * 4 + lk;      // half2 column index
            g_KVh[row0 * 128 + h2] = packh2(acc[mi][ni][0], acc[mi][ni][1]);
            g_KVh[(row0 + 8) * 128 + h2] = packh2(acc[mi][ni][2], acc[mi][ni][3]);
        }
    }
}

// =====================================================================
// K2b: attention epilogue. 8 nodes/block (warp = node), grid 1536.
// mlp_w staged via cp.async (issued first, waited at the post-attention
// barrier) so staging overlaps the attention phase.
// =====================================================================
#define K2B_SMEM ((16384 + 1024) * 4)
__global__ void __launch_bounds__(256) k2b_epi(
    const int* __restrict__ nodes, const float* __restrict__ mem_table,
    const float* __restrict__ wk_b, const float* __restrict__ wv_b,
    const float* __restrict__ ln_g, const float* __restrict__ ln_b,
    const float* __restrict__ mlp_w, const float* __restrict__ mlp_b,
    float* __restrict__ mem_out)
{
    extern __shared__ float smf[];
    float* ws  = smf;          // 16384 (mlp_w)
    float* ysm = smf + 16384;  // 1024
    const int tid = threadIdx.x, blk = blockIdx.x;

    // async stage of mlp_w: no register round-trip, overlaps attention
    {
        uint32_t wsAddr = s2u(ws);
#pragma unroll
        for (int i = 0; i < 16; i++) {
            int e = tid + i * 256;
            asm volatile("cp.async.ca.shared.global [%0], [%1], 16;"
                         :: "r"(wsAddr + (uint32_t)e * 16), "l"(mlp_w + e * 4) : "memory");
        }
        asm volatile("cp.async.commit_group;" ::: "memory");
    }

    const int w = tid >> 5, lane = tid & 31;
    const int ng = blk * 8 + w;
    const int c0 = lane * 4;
    float4 q  = *(const float4*)&g_Q[(size_t)ng * 128 + c0];
    float4 kb = *(const float4*)&wk_b[c0];
    float4 vb = *(const float4*)&wv_b[c0];
    const uint32_t* kvb = g_KVh + (size_t)ng * MS * 128;

    float a[10];
#pragma unroll
    for (int m = 0; m < 10; m++) {
        uint2 u = *(const uint2*)&kvb[m * 128 + lane * 2];
        float2 f0 = __half22float2(*(__half2*)&u.x);
        float2 f1 = __half22float2(*(__half2*)&u.y);
        float p = (f0.x + kb.x) * q.x + (f0.y + kb.y) * q.y +
                  (f1.x + kb.z) * q.z + (f1.y + kb.w) * q.w;
        p += __shfl_xor_sync(0xffffffffu, p, 8);
        p += __shfl_xor_sync(0xffffffffu, p, 4);
        p += __shfl_xor_sync(0xffffffffu, p, 2);
        p += __shfl_xor_sync(0xffffffffu, p, 1);
        a[m] = p;
    }
    float mx = -1e30f;
#pragma unroll
    for (int m = 0; m < 10; m++) {
        a[m] = (a[m] > 0.f) ? a[m] : 0.2f * a[m];
        mx = fmaxf(mx, a[m]);
    }
    float ssum = 0.f;
#pragma unroll
    for (int m = 0; m < 10; m++) { a[m] = __expf(a[m] - mx); ssum += a[m]; }
    float inv = 1.f / ssum;

    float ox = 0.f, oy = 0.f, oz = 0.f, ow = 0.f;
#pragma unroll
    for (int m = 0; m < 10; m++) {
        uint2 u = *(const uint2*)&kvb[m * 128 + 64 + lane * 2];
        float2 f0 = __half22float2(*(__half2*)&u.x);
        float2 f1 = __half22float2(*(__half2*)&u.y);
        ox += a[m] * (f0.x + vb.x); oy += a[m] * (f0.y + vb.y);
        oz += a[m] * (f1.x + vb.z); ow += a[m] * (f1.y + vb.w);
    }
    ox *= inv; oy *= inv; oz *= inv; ow *= inv;

    int node = nodes[ng];
    float4 md = *(const float4*)&mem_table[(size_t)node * 128 + c0];
    ox += md.x; oy += md.y; oz += md.z; ow += md.w;

    float s1 = ox + oy + oz + ow;
    float s2 = ox * ox + oy * oy + oz * oz + ow * ow;
#pragma unroll
    for (int off = 16; off > 0; off >>= 1) {
        s1 += __shfl_xor_sync(0xffffffffu, s1, off);
        s2 += __shfl_xor_sync(0xffffffffu, s2, off);
    }
    float mu = s1 * (1.f / 128.f);
    float var = s2 * (1.f / 128.f) - mu * mu;
    float rs = rsqrtf(var + 1e-5f);
    float4 g4 = *(const float4*)&ln_g[c0];
    float4 b4 = *(const float4*)&ln_b[c0];
    float4 y;
    y.x = (ox - mu) * rs * g4.x + b4.x;
    y.y = (oy - mu) * rs * g4.y + b4.y;
    y.z = (oz - mu) * rs * g4.z + b4.z;
    y.w = (ow - mu) * rs * g4.w + b4.w;
    *(float4*)&ysm[w * 128 + c0] = y;

    asm volatile("cp.async.wait_group 0;" ::: "memory");
    __syncthreads();

    float4 accO = *(const float4*)&mlp_b[c0];
#pragma unroll 8
    for (int k = 0; k < 128; k += 4) {
        float4 yv = *(const float4*)&ysm[w * 128 + k];
        float4 w0 = *(const float4*)&ws[(k + 0) * 128 + c0];
        float4 w1 = *(const float4*)&ws[(k + 1) * 128 + c0];
        float4 w2 = *(const float4*)&ws[(k + 2) * 128 + c0];
        float4 w3 = *(const float4*)&ws[(k + 3) * 128 + c0];
        accO.x += yv.x * w0.x + yv.y * w1.x + yv.z * w2.x + yv.w * w3.x;
        accO.y += yv.x * w0.y + yv.y * w1.y + yv.z * w2.y + yv.w * w3.y;
        accO.z += yv.x * w0.z + yv.y * w1.z + yv.z * w2.z + yv.w * w3.z;
        accO.w += yv.x * w0.w + yv.y * w1.w + yv.z * w2.w + yv.w * w3.w;
    }
    accO.x = fmaxf(accO.x, 0.f); accO.y = fmaxf(accO.y, 0.f);
    accO.z = fmaxf(accO.z, 0.f); accO.w = fmaxf(accO.w, 0.f);
    *(float4*)&mem_out[(size_t)ng * 128 + c0] = accO;
}

// =====================================================================
// K3: link head
// =====================================================================
__global__ void __launch_bounds__(128) k3_link(
    const float* __restrict__ mem_out,
    const float* __restrict__ src_w, const float* __restrict__ src_b,
    const float* __restrict__ dst_w, const float* __restrict__ dst_b,
    const float* __restrict__ out_w, const float* __restrict__ out_b,
    float* __restrict__ pos, float* __restrict__ neg)
{
    __shared__ float xsS[16 * 128], xsD[16 * 128], xsN[16 * 128];
    __shared__ float redP[16][4], redN[16][4];
    const int tid = threadIdx.x, blk = blockIdx.x;
    const int r0 = blk * 16;
#pragma unroll
    for (int r = 0; r < 16; r++) {
        xsS[r * 128 + tid] = mem_out[(size_t)(r0 + r) * 128 + tid];
        xsD[r * 128 + tid] = mem_out[(size_t)(NB + r0 + r) * 128 + tid];
        xsN[r * 128 + tid] = mem_out[(size_t)(2 * NB + r0 + r) * 128 + tid];
    }
    __syncthreads();
    float aS[16], aD[16], aN[16];
#pragma unroll
    for (int r = 0; r < 16; r++) { aS[r] = 0.f; aD[r] = 0.f; aN[r] = 0.f; }
    for (int k = 0; k < 128; k += 4) {
        float ws0 = src_w[(k + 0) * 128 + tid], ws1 = src_w[(k + 1) * 128 + tid];
        float ws2 = src_w[(k + 2) * 128 + tid], ws3 = src_w[(k + 3) * 128 + tid];
        float wd0 = dst_w[(k + 0) * 128 + tid], wd1 = dst_w[(k + 1) * 128 + tid];
        float wd2 = dst_w[(k + 2) * 128 + tid], wd3 = dst_w[(k + 3) * 128 + tid];
#pragma unroll
        for (int r = 0; r < 16; r++) {
            float4 s = *(const float4*)&xsS[r * 128 + k];
            float4 d = *(const float4*)&xsD[r * 128 + k];
            float4 n = *(const float4*)&xsN[r * 128 + k];
            aS[r] += s.x * ws0 + s.y * ws1 + s.z * ws2 + s.w * ws3;
            aD[r] += d.x * wd0 + d.y * wd1 + d.z * wd2 + d.w * wd3;
            aN[r] += n.x * wd0 + n.y * wd1 + n.z * wd2 + n.w * wd3;
        }
    }
    float ow = out_w[tid];
    float sb = src_b[tid], db = dst_b[tid];
    const int lane = tid & 31, warp = tid >> 5;
#pragma unroll
    for (int r = 0; r < 16; r++) {
        float hs = aS[r] + sb;
        float vP = fmaxf(hs + aD[r] + db, 0.f) * ow;
        float vN = fmaxf(hs + aN[r] + db, 0.f) * ow;
#pragma unroll
        for (int off = 16; off > 0; off >>= 1) {
            vP += __shfl_xor_sync(0xffffffffu, vP, off);
            vN += __shfl_xor_sync(0xffffffffu, vN, off);
        }
        if (lane == 0) { redP[r][warp] = vP; redN[r][warp] = vN; }
    }
    __syncthreads();
    float ob = out_b[0];
    if (tid < 16)
        pos[r0 + tid] = redP[tid][0] + redP[tid][1] + redP[tid][2] + redP[tid][3] + ob;
    else if (tid < 32) {
        int r = tid - 16;
        neg[r0 + r] = redN[r][0] + redN[r][1] + redN[r][2] + redN[r][3] + ob;
    }
}

// =====================================================================
// K4: CSR-style segment mean
// =====================================================================
__global__ void k4_zero() {
    int g = blockIdx.x * 256 + threadIdx.x;
    if (g < NU) g_cnt_i[g] = 0;
}

__global__ void k4_count(const int* __restrict__ src_seg) {
    int e = blockIdx.x * 256 + threadIdx.x;
    if (e < EE) atomicAdd(&g_cnt_i[src_seg[e]], 1);
}

__global__ void __launch_bounds__(256) k4_scan1() {
    __shared__ int smi[256];
    const int tid = threadIdx.x;
    int s = blockIdx.x * 256 + tid;
    int v = (s < NU) ? g_cnt_i[s] : 0;
    smi[tid] = v; __syncthreads();
    int acc = v;
#pragma unroll
    for (int off = 1; off < 256; off <<= 1) {
        int t = (tid >= off) ? smi[tid - off] : 0;
        __syncthreads();
        acc += t; smi[tid] = acc;
        __syncthreads();
    }
    if (s < NU) g_base[s] = acc - v;
    if (tid == 255) g_blksum[blockIdx.x] = acc;
}

__global__ void __launch_bounds__(256) k4_scan2() {
    __shared__ int smi[256];
    const int tid = threadIdx.x;
    int v = (tid < NSCB) ? g_blksum[tid] : 0;
    smi[tid] = v; __syncthreads();
    int acc = v;
#pragma unroll
    for (int off = 1; off < 256; off <<= 1) {
        int t = (tid >= off) ? smi[tid - off] : 0;
        __syncthreads();
        acc += t; smi[tid] = acc;
        __syncthreads();
    }
    if (tid < NSCB) g_blksum[tid] = acc - v;
}

__global__ void k4_scan3() {
    int s = blockIdx.x * 256 + threadIdx.x;
    if (s < NU) {
        int b = g_base[s] + g_blksum[s >> 8];
        g_base[s] = b;
        g_cursor[s] = b;
    }
}

__global__ void k4_scatter(const int* __restrict__ src_seg) {
    int e = blockIdx.x * 256 + threadIdx.x;
    if (e < EE) {
        int slot = atomicAdd(&g_cursor[src_seg[e]], 1);
        g_elist[slot] = e;
    }
}

__global__ void __launch_bounds__(256) k4_gather(
    const int* __restrict__ dstindex, const float* __restrict__ times,
    const float* __restrict__ mem_out, const float* __restrict__ efeat,
    float* __restrict__ o_mail, float* __restrict__ o_ts)
{
    int s = blockIdx.x * 8 + (threadIdx.x >> 5);
    if (s >= NU) return;
    const int lane = threadIdx.x & 31;
    const int c0 = lane * 4;
    int cnt = g_cnt_i[s];
    int base = g_base[s];
    float4 a0 = make_float4(0.f, 0.f, 0.f, 0.f);
    float4 a1 = a0, a2 = a0;
    float tsum = 0.f;
    for (int j = 0; j < cnt; j++) {
        int e = g_elist[base + j];
        int idx = __ldg(&dstindex[e]);
        int other = (idx < NB) ? idx + NB : idx - NB;
        int eb    = (idx < NB) ? idx : idx - NB;
        float4 v0 = *(const float4*)&mem_out[(size_t)idx * 128 + c0];
        float4 v1 = *(const float4*)&mem_out[(size_t)other * 128 + c0];
        float4 v2 = *(const float4*)&efeat[(size_t)eb * 128 + c0];
        a0.x += v0.x; a0.y += v0.y; a0.z += v0.z; a0.w += v0.w;
        a1.x += v1.x; a1.y += v1.y; a1.z += v1.z; a1.w += v1.w;
        a2.x += v2.x; a2.y += v2.y; a2.z += v2.z; a2.w += v2.w;
        tsum += __ldg(&times[idx]);
    }
    float inv = 1.f / fmaxf((float)cnt, 1.f);
    a0.x *= inv; a0.y *= inv; a0.z *= inv; a0.w *= inv;
    a1.x *= inv; a1.y *= inv; a1.z *= inv; a1.w *= inv;
    a2.x *= inv; a2.y *= inv; a2.z *= inv; a2.w *= inv;
    float* dp = o_mail + (size_t)s * 384;
    *(float4*)(dp + c0)       = a0;
    *(float4*)(dp + 128 + c0) = a1;
    *(float4*)(dp + 256 + c0) = a2;
    if (lane == 0) o_ts[s] = tsum * inv;
}

// =====================================================================
extern "C" void kernel_launch(void* const* d_in, const int* in_sizes, int n_in,
                              void* d_out, int out_size)
{
    const int*   nodes      = (const int*)  d_in[0];
    const float* times      = (const float*)d_in[1];
    const float* mem_table  = (const float*)d_in[2];
    const float* mail_table = (const float*)d_in[3];
    const float* mail_time  = (const float*)d_in[4];
    const float* efeat      = (const float*)d_in[5];
    const float* wq_w = (const float*)d_in[6],  *wq_b = (const float*)d_in[7];
    const float* wk_w = (const float*)d_in[8],  *wk_b = (const float*)d_in[9];
    const float* wv_w = (const float*)d_in[10], *wv_b = (const float*)d_in[11];
    const float* mlp_w = (const float*)d_in[12],*mlp_b = (const float*)d_in[13];
    const float* ln_g = (const float*)d_in[14], *ln_b = (const float*)d_in[15];
    const float* te_w = (const float*)d_in[16], *te_b = (const float*)d_in[17];
    const float* src_w = (const float*)d_in[18],*src_b = (const float*)d_in[19];
    const float* dst_w = (const float*)d_in[20],*dst_b = (const float*)d_in[21];
    const float* out_w = (const float*)d_in[22],*out_b = (const float*)d_in[23];
    const int* dstindex = (const int*)d_in[24];
    const int* src_seg  = (const int*)d_in[25];

    float* out    = (float*)d_out;
    float* o_mem  = out;                               // N*128
    float* o_pos  = out + (size_t)NN * 128;            // B
    float* o_neg  = o_pos + NB;                        // B
    float* o_mail = o_neg + NB;                        // NU*384
    float* o_ts   = o_mail + (size_t)NU * 384;         // NU

    static cudaStream_t sSide = nullptr;
    static cudaEvent_t eFork = nullptr, ePrep = nullptr, eMem = nullptr, eSide = nullptr;
    if (!sSide) {
        cudaStreamCreateWithFlags(&sSide, cudaStreamNonBlocking);
        cudaEventCreateWithFlags(&eFork, cudaEventDisableTiming);
        cudaEventCreateWithFlags(&ePrep, cudaEventDisableTiming);
        cudaEventCreateWithFlags(&eMem,  cudaEventDisableTiming);
        cudaEventCreateWithFlags(&eSide, cudaEventDisableTiming);
        cudaFuncSetAttribute(k2b_epi, cudaFuncAttributeMaxDynamicSharedMemorySize, K2B_SMEM);
    }

    // fork: side stream runs k1 + CSR prep concurrently with k0b+k2a
    cudaEventRecord(eFork, 0);
    cudaStreamWaitEvent(sSide, eFork, 0);

    // side stream: Q projection + segment CSR prep
    k1_q<<<NN / 32, 128, 0, sSide>>>(nodes, mem_table, wq_w, wq_b);
    k4_zero<<<NSCB, 256, 0, sSide>>>();
    k4_count<<<EE / 256, 256, 0, sSide>>>(src_seg);
    k4_scan1<<<NSCB, 256, 0, sSide>>>();
    k4_scan2<<<1, 256, 0, sSide>>>();
    k4_scan3<<<NSCB, 256, 0, sSide>>>();
    k4_scatter<<<EE / 256, 256, 0, sSide>>>(src_seg);
    cudaEventRecord(ePrep, sSide);

    // main stream: GEMM
    k0b_bsw<<<256, 256>>>(wk_w, wv_w);
    k2a_gemm<<<NBLK, 256>>>(nodes, times, mail_table, mail_time, te_w, te_b);

    // join: k2b needs g_Q (side) + g_KVh (main)
    cudaStreamWaitEvent(0, ePrep, 0);
    k2b_epi<<<NN / 8, 256, K2B_SMEM>>>(nodes, mem_table, wk_b, wv_b, ln_g, ln_b,
                                       mlp_w, mlp_b, o_mem);
    cudaEventRecord(eMem, 0);

    // fork consumers of mem_out: k4_gather on side, k3 on main
    cudaStreamWaitEvent(sSide, eMem, 0);
    k4_gather<<<NU / 8, 256, 0, sSide>>>(dstindex, times, o_mem, efeat, o_mail, o_ts);
    cudaEventRecord(eSide, sSide);

    k3_link<<<NB / 16, 128>>>(o_mem, src_w, src_b, dst_w, dst_b, out_w, out_b,
                              o_pos, o_neg);

    // final join
    cudaStreamWaitEvent(0, eSide, 0);
}

// round 17
// speedup vs baseline: 1.4602x; 1.0049x over previous
#include <cuda_runtime.h>
#include <cuda_fp16.h>
#include <math.h>
#include <stdint.h>

#define NB 4096
#define NN 12288          // 3*B
#define MS 10
#define DMSG 384
#define DKIN 484
#define EE 81920
#define NU 50000

#define RPB 64            // mail rows per k2a tile
#define NCH 16            // 16 chunks * 32 = K padded to 512
#define NBLK ((NN*MS)/RPB)  // 1920 tiles
#define K2A_GRID 296        // 2 CTAs/SM x 148 SMs (persistent)

#define NSCB ((NU + 255) / 256)        // 196 scan blocks

// ---- device scratch (static; no allocation allowed) ----
__device__ float    g_Q[NN * 128];
__device__ uint32_t g_Bh[NCH * 4096];             // fp16x2 B, slot-permuted (256 KB)
__device__ uint32_t g_KVh[(size_t)NN * MS * 128]; // 62.9 MB K|V as half2
__device__ int      g_cnt_i[NU];
__device__ int      g_base[NU];
__device__ int      g_cursor[NU];
__device__ int      g_blksum[256];
__device__ int      g_elist[EE];

// ---------------- helpers ----------------
__device__ __forceinline__ uint32_t s2u(const void* p) {
    uint32_t a;
    asm("{ .reg .u64 t; cvta.to.shared.u64 t, %1; cvt.u32.u64 %0, t; }" : "=r"(a) : "l"(p));
    return a;
}
__device__ __forceinline__ uint32_t packh2(float lo, float hi) {
    __half2 h = __floats2half2_rn(lo, hi);
    return *(uint32_t*)&h;
}
// m16n8k16 fp16 MMA, fp32 accum
__device__ __forceinline__ void mma16(float* d, uint32_t a0, uint32_t a1,
                                      uint32_t a2, uint32_t a3,
                                      uint32_t b0, uint32_t b1) {
    asm volatile(
        "mma.sync.aligned.m16n8k16.row.col.f32.f16.f16.f32 "
        "{%0,%1,%2,%3},{%4,%5,%6,%7},{%8,%9},{%0,%1,%2,%3};"
        : "+f"(d[0]), "+f"(d[1]), "+f"(d[2]), "+f"(d[3])
        : "r"(a0), "r"(a1), "r"(a2), "r"(a3), "r"(b0), "r"(b1));
}

// =====================================================================
// K0b: Wkv -> fp16x2, slot-permuted k-pair layout.
// =====================================================================
__global__ void k0b_bsw(const float* __restrict__ wk, const float* __restrict__ wv) {
    int g = blockIdx.x * 256 + threadIdx.x;   // 65536
    int kc = g >> 12;
    int rem = g & 4095;
    int n = rem >> 4, s = rem & 15;
    int p = (s & 3) * 4 + (s >> 2);
    int k = kc * 32 + 2 * p;
    float v0 = 0.f, v1 = 0.f;
    if (k < DKIN)     v0 = (n < 128) ? wk[k * 128 + n] : wv[k * 128 + (n - 128)];
    if (k + 1 < DKIN) v1 = (n < 128) ? wk[(k + 1) * 128 + n] : wv[(k + 1) * 128 + (n - 128)];
    g_Bh[g] = packh2(v0, v1);
}

// =====================================================================
// K1: Q = mem_table[nodes] @ wq_w + wq_b
// =====================================================================
__global__ void __launch_bounds__(128) k1_q(
    const int* __restrict__ nodes, const float* __restrict__ mem_table,
    const float* __restrict__ wq_w, const float* __restrict__ wq_b)
{
    __shared__ float xs[32 * 128];
    __shared__ int snode[32];
    const int tid = threadIdx.x, blk = blockIdx.x;
    if (tid < 32) snode[tid] = nodes[blk * 32 + tid];
    __syncthreads();
#pragma unroll
    for (int r = 0; r < 32; r++)
        xs[r * 128 + tid] = mem_table[(size_t)snode[r] * 128 + tid];
    __syncthreads();
    float acc[32];
#pragma unroll
    for (int r = 0; r < 32; r++) acc[r] = 0.f;
    for (int k = 0; k < 128; k += 4) {
        float w0 = wq_w[(k + 0) * 128 + tid];
        float w1 = wq_w[(k + 1) * 128 + tid];
        float w2 = wq_w[(k + 2) * 128 + tid];
        float w3 = wq_w[(k + 3) * 128 + tid];
#pragma unroll
        for (int r = 0; r < 32; r++) {
            float4 x = *(const float4*)&xs[r * 128 + k];
            acc[r] += x.x * w0 + x.y * w1 + x.z * w2 + x.w * w3;
        }
    }
    float b = wq_b[tid];
#pragma unroll
    for (int r = 0; r < 32; r++)
        g_Q[(size_t)(blk * 32 + r) * 128 + tid] = acc[r] + b;
}

// =====================================================================
// K2a: fp16 mma.sync GEMM KV[64x256] = A[64x512] @ B[512x256]
// PERSISTENT: grid=296, each CTA loops over tiles t = blk, blk+296, ...
// cpB for chunk kc+1 issued BEFORE compute(kc): L2 latency hidden.
// =====================================================================
__global__ void __launch_bounds__(256, 2) k2a_gemm(
    const int* __restrict__ nodes, const float* __restrict__ times,
    const float* __restrict__ mail_table, const float* __restrict__ mail_time,
    const float* __restrict__ te_w, const float* __restrict__ te_b)
{
    __shared__ float steW[100], steB[100], rowDt[64];
    __shared__ int rowOff[64];
    __shared__ uint32_t Ash[2][64 * 16];    // 8 KB
    __shared__ uint32_t Bsh[2][256 * 16];   // 32 KB

    const int tid = threadIdx.x;
    const int lane = tid & 31, wid = tid >> 5;
    const int warpM = wid & 1, warpN = wid >> 1;
    const int qr = lane >> 2, lk = lane & 3;

    if (tid < 100) { steW[tid] = te_w[tid]; steB[tid] = te_b[tid]; }

    uint32_t ah[2][2];
    auto genA = [&](int kc) {
#pragma unroll
        for (int i = 0; i < 2; i++) {
            int f = tid + i * 256;          // [0,512)
            int r = f >> 3, q = f & 7;
            int kbase = kc * 32 + q * 4;
            float4 v;
            if (kc < 12) {
                v = __ldg((const float4*)(mail_table + rowOff[r] + kbase));
            } else {
                int j0 = kbase - 384;
                float dt = rowDt[r];
                v.x = (j0 + 0 < 100) ? cosf(dt * steW[j0 + 0] + steB[j0 + 0]) : 0.f;
                v.y = (j0 + 1 < 100) ? cosf(dt * steW[j0 + 1] + steB[j0 + 1]) : 0.f;
                v.z = (j0 + 2 < 100) ? cosf(dt * steW[j0 + 2] + steB[j0 + 2]) : 0.f;
                v.w = (j0 + 3 < 100) ? cosf(dt * steW[j0 + 3] + steB[j0 + 3]) : 0.f;
            }
            ah[i][0] = packh2(v.x, v.y);
            ah[i][1] = packh2(v.z, v.w);
        }
    };
    auto stsA = [&](int st) {
#pragma unroll
        for (int i = 0; i < 2; i++) {
            int f = tid + i * 256;
            int r = f >> 3, q = f & 7;
            uint32_t* base = &Ash[st][r * 16];
            int p0 = 2 * q, p1 = 2 * q + 1;
            base[(p0 & 3) * 4 + (p0 >> 2)] = ah[i][0];
            base[(p1 & 3) * 4 + (p1 >> 2)] = ah[i][1];
        }
    };
    const uint32_t bshAddr = s2u(&Bsh[0][0]);
    auto cpB = [&](int kc, int st) {
        const uint32_t* src = g_Bh + kc * 4096;
#pragma unroll
        for (int i = 0; i < 4; i++) {
            int u4 = tid + i * 256;
            uint32_t dst = bshAddr + (uint32_t)st * 16384 + (uint32_t)u4 * 16;
            asm volatile("cp.async.ca.shared.global [%0], [%1], 16;"
                         :: "r"(dst), "l"(src + u4 * 4) : "memory");
        }
        asm volatile("cp.async.commit_group;" ::: "memory");
    };

#pragma unroll 1
    for (int t = blockIdx.x; t < NBLK; t += K2A_GRID) {
        __syncthreads();   // prior tile fully done: safe to overwrite rowOff & stage 0
        if (tid < RPB) {
            int g = t * RPB + tid;
            int ng = g / 10, mi = g - ng * 10;
            int nd = nodes[ng];
            rowOff[tid] = (nd * MS + mi) * DMSG;
            rowDt[tid]  = times[ng] - mail_time[nd * MS + mi];
        }
        __syncthreads();

        float acc[2][8][4];
#pragma unroll
        for (int i = 0; i < 2; i++)
#pragma unroll
            for (int j = 0; j < 8; j++)
#pragma unroll
                for (int c = 0; c < 4; c++) acc[i][j][c] = 0.f;

        auto compute = [&](int st) {
            const uint32_t* Ab = &Ash[st][0];
            const uint32_t* Bb = &Bsh[st][0];
            uint4 ua[2][2];
#pragma unroll
            for (int mi = 0; mi < 2; mi++) {
                int row = warpM * 32 + mi * 16 + qr;
                ua[mi][0] = *(const uint4*)&Ab[row * 16 + lk * 4];
                ua[mi][1] = *(const uint4*)&Ab[(row + 8) * 16 + lk * 4];
            }
#pragma unroll
            for (int h = 0; h < 2; h++) {
                uint4 vb[4];
#pragma unroll
                for (int j = 0; j < 4; j++) {
                    int n = warpN * 64 + (h * 4 + j) * 8 + qr;
                    vb[j] = *(const uint4*)&Bb[n * 16 + lk * 4];
                }
#pragma unroll
                for (int j = 0; j < 4; j++) {
                    int ni = h * 4 + j;
                    mma16(acc[0][ni], ua[0][0].x, ua[0][1].x, ua[0][0].y, ua[0][1].y,
                          vb[j].x, vb[j].y);
                    mma16(acc[1][ni], ua[1][0].x, ua[1][1].x, ua[1][0].y, ua[1][1].y,
                          vb[j].x, vb[j].y);
                    mma16(acc[0][ni], ua[0][0].z, ua[0][1].z, ua[0][0].w, ua[0][1].w,
                          vb[j].z, vb[j].w);
                    mma16(acc[1][ni], ua[1][0].z, ua[1][1].z, ua[1][0].w, ua[1][1].w,
                          vb[j].z, vb[j].w);
                }
            }
        };

        genA(0);
        stsA(0);
        cpB(0, 0);
        asm volatile("cp.async.wait_group 0;" ::: "memory");
        __syncthreads();

#pragma unroll 1
        for (int kc = 0; kc < NCH; kc++) {
            const int st = kc & 1;
            if (kc < NCH - 1) {
                cpB(kc + 1, st ^ 1);   // early issue: L2 latency under compute
                genA(kc + 1);          // LDG gather latency under compute
            }
            compute(st);
            if (kc < NCH - 1) {
                stsA(st ^ 1);
                asm volatile("cp.async.wait_group 0;" ::: "memory");
                __syncthreads();
            }
        }

        // write C to g_KVh as half2 (adjacent-column pairs)
#pragma unroll
        for (int mi = 0; mi < 2; mi++) {
#pragma unroll
            for (int ni = 0; ni < 8; ni++) {
                size_t row0 = (size_t)t * RPB + warpM * 32 + mi * 16 + qr;
                int h2 = warpN * 32 + ni * 4 + lk;      // half2 column index
                g_KVh[row0 * 128 + h2] = packh2(acc[mi][ni][0], acc[mi][ni][1]);
                g_KVh[(row0 + 8) * 128 + h2] = packh2(acc[mi][ni][2], acc[mi][ni][3]);
            }
        }
    }
}

// =====================================================================
// K2b: attention epilogue. 8 nodes/block (warp = node), grid 1536.
// mlp_w staged via cp.async (waited at the post-attention barrier).
// =====================================================================
#define K2B_SMEM ((16384 + 1024) * 4)
__global__ void __launch_bounds__(256) k2b_epi(
    const int* __restrict__ nodes, const float* __restrict__ mem_table,
    const float* __restrict__ wk_b, const float* __restrict__ wv_b,
    const float* __restrict__ ln_g, const float* __restrict__ ln_b,
    const float* __restrict__ mlp_w, const float* __restrict__ mlp_b,
    float* __restrict__ mem_out)
{
    extern __shared__ float smf[];
    float* ws  = smf;          // 16384 (mlp_w)
    float* ysm = smf + 16384;  // 1024
    const int tid = threadIdx.x, blk = blockIdx.x;

    // async stage of mlp_w: no register round-trip, overlaps attention
    {
        uint32_t wsAddr = s2u(ws);
#pragma unroll
        for (int i = 0; i < 16; i++) {
            int e = tid + i * 256;
            asm volatile("cp.async.ca.shared.global [%0], [%1], 16;"
                         :: "r"(wsAddr + (uint32_t)e * 16), "l"(mlp_w + e * 4) : "memory");
        }
        asm volatile("cp.async.commit_group;" ::: "memory");
    }

    const int w = tid >> 5, lane = tid & 31;
    const int ng = blk * 8 + w;
    const int c0 = lane * 4;
    float4 q  = *(const float4*)&g_Q[(size_t)ng * 128 + c0];
    float4 kb = *(const float4*)&wk_b[c0];
    float4 vb = *(const float4*)&wv_b[c0];
    const uint32_t* kvb = g_KVh + (size_t)ng * MS * 128;

    float a[10];
#pragma unroll
    for (int m = 0; m < 10; m++) {
        uint2 u = *(const uint2*)&kvb[m * 128 + lane * 2];
        float2 f0 = __half22float2(*(__half2*)&u.x);
        float2 f1 = __half22float2(*(__half2*)&u.y);
        float p = (f0.x + kb.x) * q.x + (f0.y + kb.y) * q.y +
                  (f1.x + kb.z) * q.z + (f1.y + kb.w) * q.w;
        p += __shfl_xor_sync(0xffffffffu, p, 8);
        p += __shfl_xor_sync(0xffffffffu, p, 4);
        p += __shfl_xor_sync(0xffffffffu, p, 2);
        p += __shfl_xor_sync(0xffffffffu, p, 1);
        a[m] = p;
    }
    float mx = -1e30f;
#pragma unroll
    for (int m = 0; m < 10; m++) {
        a[m] = (a[m] > 0.f) ? a[m] : 0.2f * a[m];
        mx = fmaxf(mx, a[m]);
    }
    float ssum = 0.f;
#pragma unroll
    for (int m = 0; m < 10; m++) { a[m] = __expf(a[m] - mx); ssum += a[m]; }
    float inv = 1.f / ssum;

    float ox = 0.f, oy = 0.f, oz = 0.f, ow = 0.f;
#pragma unroll
    for (int m = 0; m < 10; m++) {
        uint2 u = *(const uint2*)&kvb[m * 128 + 64 + lane * 2];
        float2 f0 = __half22float2(*(__half2*)&u.x);
        float2 f1 = __half22float2(*(__half2*)&u.y);
        ox += a[m] * (f0.x + vb.x); oy += a[m] * (f0.y + vb.y);
        oz += a[m] * (f1.x + vb.z); ow += a[m] * (f1.y + vb.w);
    }
    ox *= inv; oy *= inv; oz *= inv; ow *= inv;

    int node = nodes[ng];
    float4 md = *(const float4*)&mem_table[(size_t)node * 128 + c0];
    ox += md.x; oy += md.y; oz += md.z; ow += md.w;

    float s1 = ox + oy + oz + ow;
    float s2 = ox * ox + oy * oy + oz * oz + ow * ow;
#pragma unroll
    for (int off = 16; off > 0; off >>= 1) {
        s1 += __shfl_xor_sync(0xffffffffu, s1, off);
        s2 += __shfl_xor_sync(0xffffffffu, s2, off);
    }
    float mu = s1 * (1.f / 128.f);
    float var = s2 * (1.f / 128.f) - mu * mu;
    float rs = rsqrtf(var + 1e-5f);
    float4 g4 = *(const float4*)&ln_g[c0];
    float4 b4 = *(const float4*)&ln_b[c0];
    float4 y;
    y.x = (ox - mu) * rs * g4.x + b4.x;
    y.y = (oy - mu) * rs * g4.y + b4.y;
    y.z = (oz - mu) * rs * g4.z + b4.z;
    y.w = (ow - mu) * rs * g4.w + b4.w;
    *(float4*)&ysm[w * 128 + c0] = y;

    asm volatile("cp.async.wait_group 0;" ::: "memory");
    __syncthreads();

    float4 accO = *(const float4*)&mlp_b[c0];
#pragma unroll 8
    for (int k = 0; k < 128; k += 4) {
        float4 yv = *(const float4*)&ysm[w * 128 + k];
        float4 w0 = *(const float4*)&ws[(k + 0) * 128 + c0];
        float4 w1 = *(const float4*)&ws[(k + 1) * 128 + c0];
        float4 w2 = *(const float4*)&ws[(k + 2) * 128 + c0];
        float4 w3 = *(const float4*)&ws[(k + 3) * 128 + c0];
        accO.x += yv.x * w0.x + yv.y * w1.x + yv.z * w2.x + yv.w * w3.x;
        accO.y += yv.x * w0.y + yv.y * w1.y + yv.z * w2.y + yv.w * w3.y;
        accO.z += yv.x * w0.z + yv.y * w1.z + yv.z * w2.z + yv.w * w3.z;
        accO.w += yv.x * w0.w + yv.y * w1.w + yv.z * w2.w + yv.w * w3.w;
    }
    accO.x = fmaxf(accO.x, 0.f); accO.y = fmaxf(accO.y, 0.f);
    accO.z = fmaxf(accO.z, 0.f); accO.w = fmaxf(accO.w, 0.f);
    *(float4*)&mem_out[(size_t)ng * 128 + c0] = accO;
}

// =====================================================================
// K3: link head
// =====================================================================
__global__ void __launch_bounds__(128) k3_link(
    const float* __restrict__ mem_out,
    const float* __restrict__ src_w, const float* __restrict__ src_b,
    const float* __restrict__ dst_w, const float* __restrict__ dst_b,
    const float* __restrict__ out_w, const float* __restrict__ out_b,
    float* __restrict__ pos, float* __restrict__ neg)
{
    __shared__ float xsS[16 * 128], xsD[16 * 128], xsN[16 * 128];
    __shared__ float redP[16][4], redN[16][4];
    const int tid = threadIdx.x, blk = blockIdx.x;
    const int r0 = blk * 16;
#pragma unroll
    for (int r = 0; r < 16; r++) {
        xsS[r * 128 + tid] = mem_out[(size_t)(r0 + r) * 128 + tid];
        xsD[r * 128 + tid] = mem_out[(size_t)(NB + r0 + r) * 128 + tid];
        xsN[r * 128 + tid] = mem_out[(size_t)(2 * NB + r0 + r) * 128 + tid];
    }
    __syncthreads();
    float aS[16], aD[16], aN[16];
#pragma unroll
    for (int r = 0; r < 16; r++) { aS[r] = 0.f; aD[r] = 0.f; aN[r] = 0.f; }
    for (int k = 0; k < 128; k += 4) {
        float ws0 = src_w[(k + 0) * 128 + tid], ws1 = src_w[(k + 1) * 128 + tid];
        float ws2 = src_w[(k + 2) * 128 + tid], ws3 = src_w[(k + 3) * 128 + tid];
        float wd0 = dst_w[(k + 0) * 128 + tid], wd1 = dst_w[(k + 1) * 128 + tid];
        float wd2 = dst_w[(k + 2) * 128 + tid], wd3 = dst_w[(k + 3) * 128 + tid];
#pragma unroll
        for (int r = 0; r < 16; r++) {
            float4 s = *(const float4*)&xsS[r * 128 + k];
            float4 d = *(const float4*)&xsD[r * 128 + k];
            float4 n = *(const float4*)&xsN[r * 128 + k];
            aS[r] += s.x * ws0 + s.y * ws1 + s.z * ws2 + s.w * ws3;
            aD[r] += d.x * wd0 + d.y * wd1 + d.z * wd2 + d.w * wd3;
            aN[r] += n.x * wd0 + n.y * wd1 + n.z * wd2 + n.w * wd3;
        }
    }
    float ow = out_w[tid];
    float sb = src_b[tid], db = dst_b[tid];
    const int lane = tid & 31, warp = tid >> 5;
#pragma unroll
    for (int r = 0; r < 16; r++) {
        float hs = aS[r] + sb;
        float vP = fmaxf(hs + aD[r] + db, 0.f) * ow;
        float vN = fmaxf(hs + aN[r] + db, 0.f) * ow;
#pragma unroll
        for (int off = 16; off > 0; off >>= 1) {
            vP += __shfl_xor_sync(0xffffffffu, vP, off);
            vN += __shfl_xor_sync(0xffffffffu, vN, off);
        }
        if (lane == 0) { redP[r][warp] = vP; redN[r][warp] = vN; }
    }
    __syncthreads();
    float ob = out_b[0];
    if (tid < 16)
        pos[r0 + tid] = redP[tid][0] + redP[tid][1] + redP[tid][2] + redP[tid][3] + ob;
    else if (tid < 32) {
        int r = tid - 16;
        neg[r0 + r] = redN[r][0] + redN[r][1] + redN[r][2] + redN[r][3] + ob;
    }
}

// =====================================================================
// K4: CSR-style segment mean
// =====================================================================
__global__ void k4_zero() {
    int g = blockIdx.x * 256 + threadIdx.x;
    if (g < NU) g_cnt_i[g] = 0;
}

__global__ void k4_count(const int* __restrict__ src_seg) {
    int e = blockIdx.x * 256 + threadIdx.x;
    if (e < EE) atomicAdd(&g_cnt_i[src_seg[e]], 1);
}

__global__ void __launch_bounds__(256) k4_scan1() {
    __shared__ int smi[256];
    const int tid = threadIdx.x;
    int s = blockIdx.x * 256 + tid;
    int v = (s < NU) ? g_cnt_i[s] : 0;
    smi[tid] = v; __syncthreads();
    int acc = v;
#pragma unroll
    for (int off = 1; off < 256; off <<= 1) {
        int t = (tid >= off) ? smi[tid - off] : 0;
        __syncthreads();
        acc += t; smi[tid] = acc;
        __syncthreads();
    }
    if (s < NU) g_base[s] = acc - v;
    if (tid == 255) g_blksum[blockIdx.x] = acc;
}

__global__ void __launch_bounds__(256) k4_scan2() {
    __shared__ int smi[256];
    const int tid = threadIdx.x;
    int v = (tid < NSCB) ? g_blksum[tid] : 0;
    smi[tid] = v; __syncthreads();
    int acc = v;
#pragma unroll
    for (int off = 1; off < 256; off <<= 1) {
        int t = (tid >= off) ? smi[tid - off] : 0;
        __syncthreads();
        acc += t; smi[tid] = acc;
        __syncthreads();
    }
    if (tid < NSCB) g_blksum[tid] = acc - v;
}

__global__ void k4_scan3() {
    int s = blockIdx.x * 256 + threadIdx.x;
    if (s < NU) {
        int b = g_base[s] + g_blksum[s >> 8];
        g_base[s] = b;
        g_cursor[s] = b;
    }
}

__global__ void k4_scatter(const int* __restrict__ src_seg) {
    int e = blockIdx.x * 256 + threadIdx.x;
    if (e < EE) {
        int slot = atomicAdd(&g_cursor[src_seg[e]], 1);
        g_elist[slot] = e;
    }
}

__global__ void __launch_bounds__(256) k4_gather(
    const int* __restrict__ dstindex, const float* __restrict__ times,
    const float* __restrict__ mem_out, const float* __restrict__ efeat,
    float* __restrict__ o_mail, float* __restrict__ o_ts)
{
    int s = blockIdx.x * 8 + (threadIdx.x >> 5);
    if (s >= NU) return;
    const int lane = threadIdx.x & 31;
    const int c0 = lane * 4;
    int cnt = g_cnt_i[s];
    int base = g_base[s];
    float4 a0 = make_float4(0.f, 0.f, 0.f, 0.f);
    float4 a1 = a0, a2 = a0;
    float tsum = 0.f;
    for (int j = 0; j < cnt; j++) {
        int e = g_elist[base + j];
        int idx = __ldg(&dstindex[e]);
        int other = (idx < NB) ? idx + NB : idx - NB;
        int eb    = (idx < NB) ? idx : idx - NB;
        float4 v0 = *(const float4*)&mem_out[(size_t)idx * 128 + c0];
        float4 v1 = *(const float4*)&mem_out[(size_t)other * 128 + c0];
        float4 v2 = *(const float4*)&efeat[(size_t)eb * 128 + c0];
        a0.x += v0.x; a0.y += v0.y; a0.z += v0.z; a0.w += v0.w;
        a1.x += v1.x; a1.y += v1.y; a1.z += v1.z; a1.w += v1.w;
        a2.x += v2.x; a2.y += v2.y; a2.z += v2.z; a2.w += v2.w;
        tsum += __ldg(&times[idx]);
    }
    float inv = 1.f / fmaxf((float)cnt, 1.f);
    a0.x *= inv; a0.y *= inv; a0.z *= inv; a0.w *= inv;
    a1.x *= inv; a1.y *= inv; a1.z *= inv; a1.w *= inv;
    a2.x *= inv; a2.y *= inv; a2.z *= inv; a2.w *= inv;
    float* dp = o_mail + (size_t)s * 384;
    *(float4*)(dp + c0)       = a0;
    *(float4*)(dp + 128 + c0) = a1;
    *(float4*)(dp + 256 + c0) = a2;
    if (lane == 0) o_ts[s] = tsum * inv;
}

// =====================================================================
extern "C" void kernel_launch(void* const* d_in, const int* in_sizes, int n_in,
                              void* d_out, int out_size)
{
    const int*   nodes      = (const int*)  d_in[0];
    const float* times      = (const float*)d_in[1];
    const float* mem_table  = (const float*)d_in[2];
    const float* mail_table = (const float*)d_in[3];
    const float* mail_time  = (const float*)d_in[4];
    const float* efeat      = (const float*)d_in[5];
    const float* wq_w = (const float*)d_in[6],  *wq_b = (const float*)d_in[7];
    const float* wk_w = (const float*)d_in[8],  *wk_b = (const float*)d_in[9];
    const float* wv_w = (const float*)d_in[10], *wv_b = (const float*)d_in[11];
    const float* mlp_w = (const float*)d_in[12],*mlp_b = (const float*)d_in[13];
    const float* ln_g = (const float*)d_in[14], *ln_b = (const float*)d_in[15];
    const float* te_w = (const float*)d_in[16], *te_b = (const float*)d_in[17];
    const float* src_w = (const float*)d_in[18],*src_b = (const float*)d_in[19];
    const float* dst_w = (const float*)d_in[20],*dst_b = (const float*)d_in[21];
    const float* out_w = (const float*)d_in[22],*out_b = (const float*)d_in[23];
    const int* dstindex = (const int*)d_in[24];
    const int* src_seg  = (const int*)d_in[25];

    float* out    = (float*)d_out;
    float* o_mem  = out;                               // N*128
    float* o_pos  = out + (size_t)NN * 128;            // B
    float* o_neg  = o_pos + NB;                        // B
    float* o_mail = o_neg + NB;                        // NU*384
    float* o_ts   = o_mail + (size_t)NU * 384;         // NU

    static cudaStream_t sSide = nullptr;
    static cudaEvent_t eFork = nullptr, ePrep = nullptr, eMem = nullptr, eSide = nullptr;
    if (!sSide) {
        cudaStreamCreateWithFlags(&sSide, cudaStreamNonBlocking);
        cudaEventCreateWithFlags(&eFork, cudaEventDisableTiming);
        cudaEventCreateWithFlags(&ePrep, cudaEventDisableTiming);
        cudaEventCreateWithFlags(&eMem,  cudaEventDisableTiming);
        cudaEventCreateWithFlags(&eSide, cudaEventDisableTiming);
        cudaFuncSetAttribute(k2b_epi, cudaFuncAttributeMaxDynamicSharedMemorySize, K2B_SMEM);
    }

    // fork: side stream runs k1 + CSR prep concurrently with k0b+k2a
    cudaEventRecord(eFork, 0);
    cudaStreamWaitEvent(sSide, eFork, 0);

    // side stream: Q projection + segment CSR prep
    k1_q<<<NN / 32, 128, 0, sSide>>>(nodes, mem_table, wq_w, wq_b);
    k4_zero<<<NSCB, 256, 0, sSide>>>();
    k4_count<<<EE / 256, 256, 0, sSide>>>(src_seg);
    k4_scan1<<<NSCB, 256, 0, sSide>>>();
    k4_scan2<<<1, 256, 0, sSide>>>();
    k4_scan3<<<NSCB, 256, 0, sSide>>>();
    k4_scatter<<<EE / 256, 256, 0, sSide>>>(src_seg);
    cudaEventRecord(ePrep, sSide);

    // main stream: persistent GEMM
    k0b_bsw<<<256, 256>>>(wk_w, wv_w);
    k2a_gemm<<<K2A_GRID, 256>>>(nodes, times, mail_table, mail_time, te_w, te_b);

    // join: k2b needs g_Q (side) + g_KVh (main)
    cudaStreamWaitEvent(0, ePrep, 0);
    k2b_epi<<<NN / 8, 256, K2B_SMEM>>>(nodes, mem_table, wk_b, wv_b, ln_g, ln_b,
                                       mlp_w, mlp_b, o_mem);
    cudaEventRecord(eMem, 0);

    // fork consumers of mem_out: k4_gather on side, k3 on main
    cudaStreamWaitEvent(sSide, eMem, 0);
    k4_gather<<<NU / 8, 256, 0, sSide>>>(dstindex, times, o_mem, efeat, o_mail, o_ts);
    cudaEventRecord(eSide, sSide);

    k3_link<<<NB / 16, 128>>>(o_mem, src_w, src_b, dst_w, dst_b, out_w, out_b,
                              o_pos, o_neg);

    // final join
    cudaStreamWaitEvent(0, eSide, 0);
}